// round 2
// baseline (speedup 1.0000x reference)
#include <cuda_runtime.h>

// Problem constants
#define B_  64
#define H_  1024
#define I_  1024
#define BH  (B_ * H_)          // 65536
#define BHI ((size_t)BH * I_)  // 67108864

// Coefficient scratch (no cudaMalloc allowed): 3 x 256 KB
__device__ float g_common[BH];
__device__ float g_zf[BH];
__device__ float g_fz[BH];

// ---------------------------------------------------------------------------
// Kernel A: gate GEMV + scalar gate math. One warp per (b,h), h-MAJOR order:
// warps within a block share the same wm rows (L1 broadcast), adjacent blocks
// share them via L2. x (256 KB) stays resident in L1/L2.
// ---------------------------------------------------------------------------
__global__ void __launch_bounds__(256) gates_kernel(
    const float* __restrict__ x,            // [B, I]
    const float* __restrict__ hidden_prev,  // [B, H]
    const float* __restrict__ wz_state,     // [B, H]
    const float* __restrict__ wf_state,     // [B, H]
    const float* __restrict__ bz_state,     // [B, H]
    const float* __restrict__ bf_state,     // [B, H]
    const float* __restrict__ wm_z,         // [H, I]
    const float* __restrict__ wm_f,         // [H, I]
    const float* __restrict__ wv_z,         // [H]
    const float* __restrict__ wv_f,         // [H]
    const float* __restrict__ bias_z,       // [H]
    const float* __restrict__ bias_f,       // [H]
    float* __restrict__ out_cell,           // [B, H]
    float* __restrict__ out_wz,
    float* __restrict__ out_wf,
    float* __restrict__ out_bz,
    float* __restrict__ out_bf)
{
    const int w    = (blockIdx.x * blockDim.x + threadIdx.x) >> 5;  // warp id
    const int lane = threadIdx.x & 31;
    if (w >= BH) return;

    // h-major: 64 consecutive warps (8 blocks) share the same h.
    const int h = w >> 6;        // / B
    const int b = w & (B_ - 1);  // % B

    const float4* xb  = reinterpret_cast<const float4*>(x + (size_t)b * I_);
    const float4* wzr = reinterpret_cast<const float4*>(wm_z + (size_t)h * I_);
    const float4* wfr = reinterpret_cast<const float4*>(wm_f + (size_t)h * I_);

    float az = 0.f, af = 0.f;
    #pragma unroll
    for (int i = lane; i < I_ / 4; i += 32) {
        float4 xv = __ldg(xb + i);
        float4 wz = __ldg(wzr + i);
        float4 wf = __ldg(wfr + i);
        az += xv.x * wz.x + xv.y * wz.y + xv.z * wz.z + xv.w * wz.w;
        af += xv.x * wf.x + xv.y * wf.y + xv.z * wf.z + xv.w * wf.w;
    }
    #pragma unroll
    for (int o = 16; o > 0; o >>= 1) {
        az += __shfl_down_sync(0xffffffffu, az, o);
        af += __shfl_down_sync(0xffffffffu, af, o);
    }

    if (lane == 0) {
        const int bh = b * H_ + h;   // row-major (b,h) index for I/O arrays

        const float hp  = hidden_prev[bh];
        const float vz  = wv_z[h];
        const float vf  = wv_f[h];
        const float z   = tanhf(az + vz * hp + bias_z[h]);
        const float fpre = af + vf * hp + bias_f[h];
        const float f   = 1.f / (1.f + expf(-fpre));

        const float new_cell = hp * f + (1.f - f) * z;
        const float zf = (1.f - f) * (1.f - z * z);
        const float fz = (hp - z) * (1.f - f) * f;
        const float common = f + zf * vz + fz * vf;

        out_cell[bh] = new_cell;
        out_wz[bh]   = hp * zf + common * wz_state[bh];
        out_wf[bh]   = hp * fz + common * wf_state[bh];
        out_bz[bh]   = zf + common * bz_state[bh];
        out_bf[bh]   = fz + common * bf_state[bh];

        g_common[bh] = common;
        g_zf[bh]     = zf;
        g_fz[bh]     = fz;
    }
}

// ---------------------------------------------------------------------------
// Kernel B: Z_new / F_new streaming update. One thread per float4; each
// thread handles both Z and F to amortize coefficient + x loads.
// Streaming hints: Z/F are touch-once (evict-first loads, streaming stores).
// ---------------------------------------------------------------------------
__global__ void __launch_bounds__(256) state_kernel(
    const float4* __restrict__ Z,    // [B*H*I/4]
    const float4* __restrict__ F,
    const float4* __restrict__ x4,   // [B*I/4]
    float4* __restrict__ Zo,
    float4* __restrict__ Fo)
{
    const int idx = blockIdx.x * blockDim.x + threadIdx.x;  // 0 .. B*H*I/4-1
    const int row = idx >> 8;          // (b*H + h),  I/4 = 256
    const int i4  = idx & 255;
    const int b   = row >> 10;

    const float c  = __ldg(&g_common[row]);
    const float zf = __ldg(&g_zf[row]);
    const float fz = __ldg(&g_fz[row]);
    const float4 xv = __ldg(&x4[(b << 8) + i4]);

    const float4 zv = __ldcs(Z + idx);
    const float4 fv = __ldcs(F + idx);

    float4 zo, fo;
    zo.x = c * zv.x + zf * xv.x;
    zo.y = c * zv.y + zf * xv.y;
    zo.z = c * zv.z + zf * xv.z;
    zo.w = c * zv.w + zf * xv.w;
    fo.x = c * fv.x + fz * xv.x;
    fo.y = c * fv.y + fz * xv.y;
    fo.z = c * fv.z + fz * xv.z;
    fo.w = c * fv.w + fz * xv.w;

    __stcs(Zo + idx, zo);
    __stcs(Fo + idx, fo);
}

// ---------------------------------------------------------------------------
extern "C" void kernel_launch(void* const* d_in, const int* in_sizes, int n_in,
                              void* d_out, int out_size)
{
    const float* x           = (const float*)d_in[0];
    const float* hidden_prev = (const float*)d_in[1];
    const float* Z_state     = (const float*)d_in[2];
    const float* F_state     = (const float*)d_in[3];
    const float* wz_state    = (const float*)d_in[4];
    const float* wf_state    = (const float*)d_in[5];
    const float* bz_state    = (const float*)d_in[6];
    const float* bf_state    = (const float*)d_in[7];
    const float* wm_z        = (const float*)d_in[8];
    const float* wm_f        = (const float*)d_in[9];
    const float* wv_z        = (const float*)d_in[10];
    const float* wv_f        = (const float*)d_in[11];
    const float* bias_z      = (const float*)d_in[12];
    const float* bias_f      = (const float*)d_in[13];

    float* out = (float*)d_out;
    // Output tuple layout: new_cell, Z_new, F_new, wz_new, wf_new, bz_new, bf_new
    float* o_cell = out;
    float* o_Z    = out + BH;
    float* o_F    = o_Z + BHI;
    float* o_wz   = o_F + BHI;
    float* o_wf   = o_wz + BH;
    float* o_bz   = o_wf + BH;
    float* o_bf   = o_bz + BH;

    // Kernel A: 65536 warps -> 8192 blocks of 256 threads
    gates_kernel<<<(BH * 32) / 256, 256>>>(
        x, hidden_prev, wz_state, wf_state, bz_state, bf_state,
        wm_z, wm_f, wv_z, wv_f, bias_z, bias_f,
        o_cell, o_wz, o_wf, o_bz, o_bf);

    // Kernel B: B*H*I/4 = 16,777,216 float4 threads
    const int total4 = (int)(BHI / 4);
    state_kernel<<<total4 / 256, 256>>>(
        (const float4*)Z_state, (const float4*)F_state, (const float4*)x,
        (float4*)o_Z, (float4*)o_F);
}

// round 3
// speedup vs baseline: 1.0771x; 1.0771x over previous
#include <cuda_runtime.h>

// Problem constants
#define B_  64
#define H_  1024
#define I_  1024
#define BH  (B_ * H_)          // 65536
#define BHI ((size_t)BH * I_)  // 67108864

#define BTILE 16               // batch rows per block (x tile in smem)
#define HPB   8                // h rows per block (one per warp)

// Coefficient scratch (no cudaMalloc allowed): 3 x 256 KB
__device__ float g_common[BH];
__device__ float g_zf[BH];
__device__ float g_fz[BH];

// ---------------------------------------------------------------------------
// Kernel A: gate GEMV with register-resident weights.
// Grid: (H/HPB, B/BTILE). Block: 256 threads = 8 warps.
// Each warp owns one h: loads wm_z[h], wm_f[h] chunks into registers ONCE,
// then dots against BTILE x-rows staged in shared memory.
// wm L1 traffic: 512 MB -> 32 MB. x: smem-resident.
// ---------------------------------------------------------------------------
__global__ void __launch_bounds__(256) gates_kernel(
    const float* __restrict__ x,            // [B, I]
    const float* __restrict__ hidden_prev,  // [B, H]
    const float* __restrict__ wz_state,     // [B, H]
    const float* __restrict__ wf_state,     // [B, H]
    const float* __restrict__ bz_state,     // [B, H]
    const float* __restrict__ bf_state,     // [B, H]
    const float* __restrict__ wm_z,         // [H, I]
    const float* __restrict__ wm_f,         // [H, I]
    const float* __restrict__ wv_z,         // [H]
    const float* __restrict__ wv_f,         // [H]
    const float* __restrict__ bias_z,       // [H]
    const float* __restrict__ bias_f,       // [H]
    float* __restrict__ out_cell,           // [B, H]
    float* __restrict__ out_wz,
    float* __restrict__ out_wf,
    float* __restrict__ out_bz,
    float* __restrict__ out_bf)
{
    __shared__ float4 x_s[BTILE * (I_ / 4)];        // 64 KB
    __shared__ float  acc_s[HPB][2][BTILE];         // per-warp dot results

    const int tid  = threadIdx.x;
    const int wid  = tid >> 5;
    const int lane = tid & 31;

    const int h      = blockIdx.x * HPB + wid;
    const int b_base = blockIdx.y * BTILE;

    // ---- stage x tile: BTILE rows x I_ floats, coalesced float4 loads ----
    {
        const float4* xg = reinterpret_cast<const float4*>(x + (size_t)b_base * I_);
        #pragma unroll
        for (int j = 0; j < (BTILE * I_ / 4) / 256; ++j)
            x_s[tid + j * 256] = __ldg(xg + tid + j * 256);
    }

    // ---- load this warp's weight rows into registers ----
    // lane covers float4 indices: lane + k*32, k = 0..7  (I/4 = 256)
    const float4* wzr = reinterpret_cast<const float4*>(wm_z + (size_t)h * I_);
    const float4* wfr = reinterpret_cast<const float4*>(wm_f + (size_t)h * I_);
    float4 wz[8], wf[8];
    #pragma unroll
    for (int k = 0; k < 8; ++k) {
        wz[k] = __ldg(wzr + lane + k * 32);
        wf[k] = __ldg(wfr + lane + k * 32);
    }

    __syncthreads();

    // ---- dot products: reuse register weights across BTILE batch rows ----
    #pragma unroll
    for (int b = 0; b < BTILE; ++b) {
        float az = 0.f, af = 0.f;
        const float4* xr = x_s + b * (I_ / 4);
        #pragma unroll
        for (int k = 0; k < 8; ++k) {
            float4 xv = xr[lane + k * 32];
            az += xv.x * wz[k].x + xv.y * wz[k].y + xv.z * wz[k].z + xv.w * wz[k].w;
            af += xv.x * wf[k].x + xv.y * wf[k].y + xv.z * wf[k].z + xv.w * wf[k].w;
        }
        #pragma unroll
        for (int o = 16; o > 0; o >>= 1) {
            az += __shfl_down_sync(0xffffffffu, az, o);
            af += __shfl_down_sync(0xffffffffu, af, o);
        }
        if (lane == 0) { acc_s[wid][0][b] = az; acc_s[wid][1][b] = af; }
    }
    __syncwarp();

    // ---- epilogue: lanes 0..BTILE-1 each handle one batch row ----
    if (lane < BTILE) {
        const int b  = b_base + lane;
        const int bh = b * H_ + h;

        const float az = acc_s[wid][0][lane];
        const float af = acc_s[wid][1][lane];

        const float hp   = hidden_prev[bh];
        const float vz   = wv_z[h];
        const float vf   = wv_f[h];
        const float z    = tanhf(az + vz * hp + bias_z[h]);
        const float fpre = af + vf * hp + bias_f[h];
        const float f    = 1.f / (1.f + expf(-fpre));

        const float new_cell = hp * f + (1.f - f) * z;
        const float zf = (1.f - f) * (1.f - z * z);
        const float fz = (hp - z) * (1.f - f) * f;
        const float common = f + zf * vz + fz * vf;

        out_cell[bh] = new_cell;
        out_wz[bh]   = hp * zf + common * wz_state[bh];
        out_wf[bh]   = hp * fz + common * wf_state[bh];
        out_bz[bh]   = zf + common * bz_state[bh];
        out_bf[bh]   = fz + common * bf_state[bh];

        g_common[bh] = common;
        g_zf[bh]     = zf;
        g_fz[bh]     = fz;
    }
}

// ---------------------------------------------------------------------------
// Kernel B: Z_new / F_new streaming update. One thread per float4; each
// thread handles both Z and F to amortize coefficient + x loads.
// Streaming hints: Z/F are touch-once (evict-first loads, streaming stores).
// ---------------------------------------------------------------------------
__global__ void __launch_bounds__(256) state_kernel(
    const float4* __restrict__ Z,    // [B*H*I/4]
    const float4* __restrict__ F,
    const float4* __restrict__ x4,   // [B*I/4]
    float4* __restrict__ Zo,
    float4* __restrict__ Fo)
{
    const int idx = blockIdx.x * blockDim.x + threadIdx.x;  // 0 .. B*H*I/4-1
    const int row = idx >> 8;          // (b*H + h),  I/4 = 256
    const int i4  = idx & 255;
    const int b   = row >> 10;

    const float c  = __ldg(&g_common[row]);
    const float zf = __ldg(&g_zf[row]);
    const float fz = __ldg(&g_fz[row]);
    const float4 xv = __ldg(&x4[(b << 8) + i4]);

    const float4 zv = __ldcs(Z + idx);
    const float4 fv = __ldcs(F + idx);

    float4 zo, fo;
    zo.x = c * zv.x + zf * xv.x;
    zo.y = c * zv.y + zf * xv.y;
    zo.z = c * zv.z + zf * xv.z;
    zo.w = c * zv.w + zf * xv.w;
    fo.x = c * fv.x + fz * xv.x;
    fo.y = c * fv.y + fz * xv.y;
    fo.z = c * fv.z + fz * xv.z;
    fo.w = c * fv.w + fz * xv.w;

    __stcs(Zo + idx, zo);
    __stcs(Fo + idx, fo);
}

// ---------------------------------------------------------------------------
extern "C" void kernel_launch(void* const* d_in, const int* in_sizes, int n_in,
                              void* d_out, int out_size)
{
    const float* x           = (const float*)d_in[0];
    const float* hidden_prev = (const float*)d_in[1];
    const float* Z_state     = (const float*)d_in[2];
    const float* F_state     = (const float*)d_in[3];
    const float* wz_state    = (const float*)d_in[4];
    const float* wf_state    = (const float*)d_in[5];
    const float* bz_state    = (const float*)d_in[6];
    const float* bf_state    = (const float*)d_in[7];
    const float* wm_z        = (const float*)d_in[8];
    const float* wm_f        = (const float*)d_in[9];
    const float* wv_z        = (const float*)d_in[10];
    const float* wv_f        = (const float*)d_in[11];
    const float* bias_z      = (const float*)d_in[12];
    const float* bias_f      = (const float*)d_in[13];

    float* out = (float*)d_out;
    // Output tuple layout: new_cell, Z_new, F_new, wz_new, wf_new, bz_new, bf_new
    float* o_cell = out;
    float* o_Z    = out + BH;
    float* o_F    = o_Z + BHI;
    float* o_wz   = o_F + BHI;
    float* o_wf   = o_wz + BH;
    float* o_bz   = o_wf + BH;
    float* o_bf   = o_bz + BH;

    // Kernel A: grid (H/HPB, B/BTILE) = (128, 4) blocks of 256 threads
    dim3 gridA(H_ / HPB, B_ / BTILE);
    gates_kernel<<<gridA, 256>>>(
        x, hidden_prev, wz_state, wf_state, bz_state, bf_state,
        wm_z, wm_f, wv_z, wv_f, bias_z, bias_f,
        o_cell, o_wz, o_wf, o_bz, o_bf);

    // Kernel B: B*H*I/4 = 16,777,216 float4 threads
    const int total4 = (int)(BHI / 4);
    state_kernel<<<total4 / 256, 256>>>(
        (const float4*)Z_state, (const float4*)F_state, (const float4*)x,
        (float4*)o_Z, (float4*)o_F);
}

// round 4
// speedup vs baseline: 1.2076x; 1.1212x over previous
#include <cuda_runtime.h>

// Problem constants
#define B_  64
#define H_  1024
#define I_  1024
#define BH  (B_ * H_)          // 65536
#define BHI ((size_t)BH * I_)  // 67108864

// ---------------------------------------------------------------------------
// Fully fused kernel: one 256-thread block per (b,h) row.
//   - each thread owns one float4 column chunk (I/4 = 256 = blockDim)
//   - issues streaming Z/F row loads FIRST (overlap with reduction latency)
//   - computes the two gate dot-products via block reduction
//   - thread 0 does the scalar gate math + small outputs, broadcasts coeffs
//   - all threads do the Z_new/F_new FMA + streaming stores
// GEMV traffic (x, wm rows: L2-resident) hides under DRAM-bound streaming.
// ---------------------------------------------------------------------------
__global__ void __launch_bounds__(256) fused_kernel(
    const float4* __restrict__ x4,     // [B, I/4]
    const float*  __restrict__ hidden_prev,
    const float4* __restrict__ Z,      // [BH, I/4]
    const float4* __restrict__ F,
    const float*  __restrict__ wz_state,
    const float*  __restrict__ wf_state,
    const float*  __restrict__ bz_state,
    const float*  __restrict__ bf_state,
    const float4* __restrict__ wmz4,   // [H, I/4]
    const float4* __restrict__ wmf4,
    const float*  __restrict__ wv_z,   // [H]
    const float*  __restrict__ wv_f,
    const float*  __restrict__ bias_z,
    const float*  __restrict__ bias_f,
    float*  __restrict__ out_cell,     // [B, H]
    float4* __restrict__ Zo,
    float4* __restrict__ Fo,
    float*  __restrict__ out_wz,
    float*  __restrict__ out_wf,
    float*  __restrict__ out_bz,
    float*  __restrict__ out_bf)
{
    __shared__ float red[2][8];
    __shared__ float coef[3];

    const int bh   = blockIdx.x;          // = b*H + h (row-major)
    const int b    = bh >> 10;
    const int h    = bh & (H_ - 1);
    const int t    = threadIdx.x;
    const int wid  = t >> 5;
    const int lane = t & 31;

    const size_t row = (size_t)bh << 8;   // float4 offset of this row

    // ---- issue the big streaming loads first (evict-first: touch-once) ----
    const float4 zv = __ldcs(Z + row + t);
    const float4 fv = __ldcs(F + row + t);

    // ---- GEMV operands (hot in L1/L2) ----
    const float4 xv  = __ldg(x4   + ((size_t)b << 8) + t);
    const float4 wzv = __ldg(wmz4 + ((size_t)h << 8) + t);
    const float4 wfv = __ldg(wmf4 + ((size_t)h << 8) + t);

    float az = xv.x * wzv.x + xv.y * wzv.y + xv.z * wzv.z + xv.w * wzv.w;
    float af = xv.x * wfv.x + xv.y * wfv.y + xv.z * wfv.z + xv.w * wfv.w;

    #pragma unroll
    for (int o = 16; o > 0; o >>= 1) {
        az += __shfl_down_sync(0xffffffffu, az, o);
        af += __shfl_down_sync(0xffffffffu, af, o);
    }
    if (lane == 0) { red[0][wid] = az; red[1][wid] = af; }
    __syncthreads();

    if (t == 0) {
        float AZ = 0.f, AF = 0.f;
        #pragma unroll
        for (int j = 0; j < 8; ++j) { AZ += red[0][j]; AF += red[1][j]; }

        const float hp   = hidden_prev[bh];
        const float vz   = wv_z[h];
        const float vf   = wv_f[h];
        const float z    = tanhf(AZ + vz * hp + bias_z[h]);
        const float fpre = AF + vf * hp + bias_f[h];
        const float f    = 1.f / (1.f + expf(-fpre));

        const float new_cell = hp * f + (1.f - f) * z;
        const float zf = (1.f - f) * (1.f - z * z);
        const float fz = (hp - z) * (1.f - f) * f;
        const float common = f + zf * vz + fz * vf;

        out_cell[bh] = new_cell;
        out_wz[bh]   = hp * zf + common * wz_state[bh];
        out_wf[bh]   = hp * fz + common * wf_state[bh];
        out_bz[bh]   = zf + common * bz_state[bh];
        out_bf[bh]   = fz + common * bf_state[bh];

        coef[0] = common; coef[1] = zf; coef[2] = fz;
    }
    __syncthreads();

    const float c   = coef[0];
    const float czf = coef[1];
    const float cfz = coef[2];

    float4 zo, fo;
    zo.x = c * zv.x + czf * xv.x;
    zo.y = c * zv.y + czf * xv.y;
    zo.z = c * zv.z + czf * xv.z;
    zo.w = c * zv.w + czf * xv.w;
    fo.x = c * fv.x + cfz * xv.x;
    fo.y = c * fv.y + cfz * xv.y;
    fo.z = c * fv.z + cfz * xv.z;
    fo.w = c * fv.w + cfz * xv.w;

    __stcs(Zo + row + t, zo);
    __stcs(Fo + row + t, fo);
}

// ---------------------------------------------------------------------------
extern "C" void kernel_launch(void* const* d_in, const int* in_sizes, int n_in,
                              void* d_out, int out_size)
{
    const float* x           = (const float*)d_in[0];
    const float* hidden_prev = (const float*)d_in[1];
    const float* Z_state     = (const float*)d_in[2];
    const float* F_state     = (const float*)d_in[3];
    const float* wz_state    = (const float*)d_in[4];
    const float* wf_state    = (const float*)d_in[5];
    const float* bz_state    = (const float*)d_in[6];
    const float* bf_state    = (const float*)d_in[7];
    const float* wm_z        = (const float*)d_in[8];
    const float* wm_f        = (const float*)d_in[9];
    const float* wv_z        = (const float*)d_in[10];
    const float* wv_f        = (const float*)d_in[11];
    const float* bias_z      = (const float*)d_in[12];
    const float* bias_f      = (const float*)d_in[13];

    float* out = (float*)d_out;
    // Output tuple layout: new_cell, Z_new, F_new, wz_new, wf_new, bz_new, bf_new
    float* o_cell = out;
    float* o_Z    = out + BH;
    float* o_F    = o_Z + BHI;
    float* o_wz   = o_F + BHI;
    float* o_wf   = o_wz + BH;
    float* o_bz   = o_wf + BH;
    float* o_bf   = o_bz + BH;

    fused_kernel<<<BH, 256>>>(
        (const float4*)x, hidden_prev,
        (const float4*)Z_state, (const float4*)F_state,
        wz_state, wf_state, bz_state, bf_state,
        (const float4*)wm_z, (const float4*)wm_f,
        wv_z, wv_f, bias_z, bias_f,
        o_cell, (float4*)o_Z, (float4*)o_F,
        o_wz, o_wf, o_bz, o_bf);
}

// round 5
// speedup vs baseline: 1.2184x; 1.0089x over previous
#include <cuda_runtime.h>

// Problem constants
#define B_  64
#define H_  1024
#define I_  1024
#define BH  (B_ * H_)          // 65536
#define BHI ((size_t)BH * I_)  // 67108864
#define ROWS 4                 // (b,h) rows per block; consecutive bh share b

// ---------------------------------------------------------------------------
// Fused kernel, 4 rows per 256-thread block.
//   - streaming Z/F loads for all 4 rows issued first (8 float4 in flight)
//   - gate GEMV partials for all 4 rows against one shared x row (register xv)
//   - single barrier pair per 4 rows; epilogue parallelized over threads 0..3
//     with their scalar operands preloaded at kernel start
// ---------------------------------------------------------------------------
__global__ void __launch_bounds__(256) fused_kernel(
    const float4* __restrict__ x4,     // [B, I/4]
    const float*  __restrict__ hidden_prev,
    const float4* __restrict__ Z,      // [BH, I/4]
    const float4* __restrict__ F,
    const float*  __restrict__ wz_state,
    const float*  __restrict__ wf_state,
    const float*  __restrict__ bz_state,
    const float*  __restrict__ bf_state,
    const float4* __restrict__ wmz4,   // [H, I/4]
    const float4* __restrict__ wmf4,
    const float*  __restrict__ wv_z,   // [H]
    const float*  __restrict__ wv_f,
    const float*  __restrict__ bias_z,
    const float*  __restrict__ bias_f,
    float*  __restrict__ out_cell,     // [B, H]
    float4* __restrict__ Zo,
    float4* __restrict__ Fo,
    float*  __restrict__ out_wz,
    float*  __restrict__ out_wf,
    float*  __restrict__ out_bz,
    float*  __restrict__ out_bf)
{
    __shared__ float red[8][2 * ROWS];   // [warp][r*2 + gate]
    __shared__ float coef[3][ROWS];

    const int bh0  = blockIdx.x * ROWS;
    const int b    = bh0 >> 10;
    const int h0   = bh0 & (H_ - 1);
    const int t    = threadIdx.x;
    const int wid  = t >> 5;
    const int lane = t & 31;

    const size_t row0 = (size_t)bh0 << 8;   // float4 offset of first row

    // ---- streaming loads for all 4 rows, issued first (touch-once) ----
    float4 zv[ROWS], fv[ROWS];
    #pragma unroll
    for (int r = 0; r < ROWS; ++r) {
        zv[r] = __ldcs(Z + row0 + (size_t)(r << 8) + t);
        fv[r] = __ldcs(F + row0 + (size_t)(r << 8) + t);
    }

    // ---- epilogue scalar preloads: threads 0..3, one row each ----
    float hp = 0.f, wzs = 0.f, wfs = 0.f, bzs = 0.f, bfs = 0.f;
    float vz = 0.f, vf = 0.f, bsz = 0.f, bsf = 0.f;
    if (t < ROWS) {
        const int bh = bh0 + t;
        const int h  = h0 + t;
        hp  = hidden_prev[bh];
        wzs = wz_state[bh];  wfs = wf_state[bh];
        bzs = bz_state[bh];  bfs = bf_state[bh];
        vz  = wv_z[h];       vf  = wv_f[h];
        bsz = bias_z[h];     bsf = bias_f[h];
    }

    // ---- GEMV partials: one x chunk, 4 wm_z/wm_f row chunks (L2-hot) ----
    const float4 xv = __ldg(x4 + ((size_t)b << 8) + t);
    float pz[ROWS], pf[ROWS];
    #pragma unroll
    for (int r = 0; r < ROWS; ++r) {
        const float4 wzv = __ldg(wmz4 + ((size_t)(h0 + r) << 8) + t);
        const float4 wfv = __ldg(wmf4 + ((size_t)(h0 + r) << 8) + t);
        pz[r] = xv.x * wzv.x + xv.y * wzv.y + xv.z * wzv.z + xv.w * wzv.w;
        pf[r] = xv.x * wfv.x + xv.y * wfv.y + xv.z * wfv.z + xv.w * wfv.w;
    }
    #pragma unroll
    for (int o = 16; o > 0; o >>= 1) {
        #pragma unroll
        for (int r = 0; r < ROWS; ++r) {
            pz[r] += __shfl_xor_sync(0xffffffffu, pz[r], o);
            pf[r] += __shfl_xor_sync(0xffffffffu, pf[r], o);
        }
    }
    if (lane == 0) {
        #pragma unroll
        for (int r = 0; r < ROWS; ++r) {
            red[wid][r * 2]     = pz[r];
            red[wid][r * 2 + 1] = pf[r];
        }
    }
    __syncthreads();

    // ---- epilogue: threads 0..3 in parallel, operands already in regs ----
    if (t < ROWS) {
        float AZ = 0.f, AF = 0.f;
        #pragma unroll
        for (int w = 0; w < 8; ++w) {
            AZ += red[w][t * 2];
            AF += red[w][t * 2 + 1];
        }

        const int bh = bh0 + t;
        const float z    = tanhf(AZ + vz * hp + bsz);
        const float fpre = AF + vf * hp + bsf;
        const float f    = 1.f / (1.f + expf(-fpre));

        const float zf = (1.f - f) * (1.f - z * z);
        const float fz = (hp - z) * (1.f - f) * f;
        const float common = f + zf * vz + fz * vf;

        out_cell[bh] = hp * f + (1.f - f) * z;
        out_wz[bh]   = hp * zf + common * wzs;
        out_wf[bh]   = hp * fz + common * wfs;
        out_bz[bh]   = zf + common * bzs;
        out_bf[bh]   = fz + common * bfs;

        coef[0][t] = common;
        coef[1][t] = zf;
        coef[2][t] = fz;
    }
    __syncthreads();

    // ---- streaming FMA + stores for all 4 rows ----
    #pragma unroll
    for (int r = 0; r < ROWS; ++r) {
        const float c   = coef[0][r];
        const float czf = coef[1][r];
        const float cfz = coef[2][r];

        float4 zo, fo;
        zo.x = c * zv[r].x + czf * xv.x;
        zo.y = c * zv[r].y + czf * xv.y;
        zo.z = c * zv[r].z + czf * xv.z;
        zo.w = c * zv[r].w + czf * xv.w;
        fo.x = c * fv[r].x + cfz * xv.x;
        fo.y = c * fv[r].y + cfz * xv.y;
        fo.z = c * fv[r].z + cfz * xv.z;
        fo.w = c * fv[r].w + cfz * xv.w;

        __stcs(Zo + row0 + (size_t)(r << 8) + t, zo);
        __stcs(Fo + row0 + (size_t)(r << 8) + t, fo);
    }
}

// ---------------------------------------------------------------------------
extern "C" void kernel_launch(void* const* d_in, const int* in_sizes, int n_in,
                              void* d_out, int out_size)
{
    const float* x           = (const float*)d_in[0];
    const float* hidden_prev = (const float*)d_in[1];
    const float* Z_state     = (const float*)d_in[2];
    const float* F_state     = (const float*)d_in[3];
    const float* wz_state    = (const float*)d_in[4];
    const float* wf_state    = (const float*)d_in[5];
    const float* bz_state    = (const float*)d_in[6];
    const float* bf_state    = (const float*)d_in[7];
    const float* wm_z        = (const float*)d_in[8];
    const float* wm_f        = (const float*)d_in[9];
    const float* wv_z        = (const float*)d_in[10];
    const float* wv_f        = (const float*)d_in[11];
    const float* bias_z      = (const float*)d_in[12];
    const float* bias_f      = (const float*)d_in[13];

    float* out = (float*)d_out;
    // Output tuple layout: new_cell, Z_new, F_new, wz_new, wf_new, bz_new, bf_new
    float* o_cell = out;
    float* o_Z    = out + BH;
    float* o_F    = o_Z + BHI;
    float* o_wz   = o_F + BHI;
    float* o_wf   = o_wz + BH;
    float* o_bz   = o_wf + BH;
    float* o_bf   = o_bz + BH;

    fused_kernel<<<BH / ROWS, 256>>>(
        (const float4*)x, hidden_prev,
        (const float4*)Z_state, (const float4*)F_state,
        wz_state, wf_state, bz_state, bf_state,
        (const float4*)wm_z, (const float4*)wm_f,
        wv_z, wv_f, bias_z, bias_f,
        o_cell, (float4*)o_Z, (float4*)o_F,
        o_wz, o_wf, o_bz, o_bf);
}